// round 3
// baseline (speedup 1.0000x reference)
#include <cuda_runtime.h>
#include <cstdint>

#define BDIM 64
#define TDIM 2048
#define DDIM 256
#define HDIM 256
#define G3   768

// Scratch for the input projection xg = x @ W_ih^T + b_ih : [B*T, 3H] fp32
__device__ float g_xg[(size_t)BDIM * TDIM * G3];

// ---------------- f32x2 helpers (Blackwell packed fp32) ----------------
__device__ __forceinline__ unsigned long long pk2(float x, float y) {
    unsigned long long r;
    asm("mov.b64 %0, {%1, %2};" : "=l"(r) : "f"(x), "f"(y));
    return r;
}
__device__ __forceinline__ void upk2(unsigned long long p, float& x, float& y) {
    asm("mov.b64 {%0, %1}, %2;" : "=f"(x), "=f"(y) : "l"(p));
}
__device__ __forceinline__ unsigned long long fma2(unsigned long long a,
                                                   unsigned long long b,
                                                   unsigned long long c) {
    unsigned long long d;
    asm("fma.rn.f32x2 %0, %1, %2, %3;" : "=l"(d) : "l"(a), "l"(b), "l"(c));
    return d;
}

// ---------------- Kernel 1: projection GEMM (unchanged, known-good) ----------------
#define BM 64
#define BN 64
#define BK 32

__global__ __launch_bounds__(256) void proj_gemm(const float* __restrict__ x,
                                                 const float* __restrict__ W,
                                                 const float* __restrict__ bias) {
    __shared__ float As[BK][BM + 4];
    __shared__ float Bs[BK][BN + 4];
    const int tid = threadIdx.x;
    const int gm = blockIdx.x * BM;
    const int gn = blockIdx.y * BN;
    const int m4 = (tid >> 4) * 4;
    const int n4 = (tid & 15) * 4;

    unsigned long long acc[4][2];
#pragma unroll
    for (int i = 0; i < 4; i++) { acc[i][0] = 0ull; acc[i][1] = 0ull; }

    for (int kt = 0; kt < DDIM; kt += BK) {
#pragma unroll
        for (int j = 0; j < 2; j++) {
            int idx = tid + j * 256;
            int row = idx >> 3;
            int c4  = (idx & 7) * 4;
            float4 va = *(const float4*)&x[(size_t)(gm + row) * DDIM + kt + c4];
            As[c4 + 0][row] = va.x; As[c4 + 1][row] = va.y;
            As[c4 + 2][row] = va.z; As[c4 + 3][row] = va.w;
            float4 vb = *(const float4*)&W[(size_t)(gn + row) * DDIM + kt + c4];
            Bs[c4 + 0][row] = vb.x; Bs[c4 + 1][row] = vb.y;
            Bs[c4 + 2][row] = vb.z; Bs[c4 + 3][row] = vb.w;
        }
        __syncthreads();
#pragma unroll
        for (int k = 0; k < BK; k++) {
            float4 av = *(const float4*)&As[k][m4];
            float4 bv = *(const float4*)&Bs[k][n4];
            unsigned long long bp0 = pk2(bv.x, bv.y);
            unsigned long long bp1 = pk2(bv.z, bv.w);
            unsigned long long aa;
            aa = pk2(av.x, av.x);
            acc[0][0] = fma2(aa, bp0, acc[0][0]); acc[0][1] = fma2(aa, bp1, acc[0][1]);
            aa = pk2(av.y, av.y);
            acc[1][0] = fma2(aa, bp0, acc[1][0]); acc[1][1] = fma2(aa, bp1, acc[1][1]);
            aa = pk2(av.z, av.z);
            acc[2][0] = fma2(aa, bp0, acc[2][0]); acc[2][1] = fma2(aa, bp1, acc[2][1]);
            aa = pk2(av.w, av.w);
            acc[3][0] = fma2(aa, bp0, acc[3][0]); acc[3][1] = fma2(aa, bp1, acc[3][1]);
        }
        __syncthreads();
    }

    float4 bb = *(const float4*)&bias[gn + n4];
#pragma unroll
    for (int mi = 0; mi < 4; mi++) {
        float o0, o1, o2, o3;
        upk2(acc[mi][0], o0, o1);
        upk2(acc[mi][1], o2, o3);
        float4 o = make_float4(o0 + bb.x, o1 + bb.y, o2 + bb.z, o3 + bb.w);
        *(float4*)&g_xg[(size_t)(gm + m4 + mi) * G3 + gn + n4] = o;
    }
}

// ---------------- Kernel 2: register-W recurrence, cluster-8, plain-DSMEM sync ----------------
// 16 clusters x 8 CTAs. Cluster owns 4 batches; CTA rank owns 32 h-indices
// (96 W_hh rows held in registers: 32 packed f32x2 per lane).
// h exchanged per step via PLAIN st.shared::cluster + one cluster barrier.
#define CLSZ 8
#define RTH  384
#define IDXC 32
#define NROW 96
#define BB   4

__device__ __forceinline__ float sigm_f(float x) { return 1.f / (1.f + __expf(-x)); }
__device__ __forceinline__ float tanh_f(float x) { return 1.f - 2.f / (__expf(2.f * x) + 1.f); }

__device__ __forceinline__ void st_dsmem_u64(uint32_t saddr, uint32_t rk, unsigned long long v) {
    uint32_t ra;
    asm volatile("mapa.shared::cluster.u32 %0, %1, %2;" : "=r"(ra) : "r"(saddr), "r"(rk));
    asm volatile("st.shared::cluster.u64 [%0], %1;" :: "r"(ra), "l"(v) : "memory");
}
__device__ __forceinline__ void cluster_barrier() {
    asm volatile("barrier.cluster.arrive.aligned;" ::: "memory");
    asm volatile("barrier.cluster.wait.aligned;" ::: "memory");
}

__global__ __launch_bounds__(RTH, 1) void gru_rec(const float* __restrict__ h0,
                                                  const float* __restrict__ W_hh,
                                                  const float* __restrict__ b_hh,
                                                  float* __restrict__ hs,
                                                  float* __restrict__ hT) {
    __shared__ alignas(16) float sh_h[2][BB * HDIM];   // [buf][b][k]
    __shared__ alignas(16) float sh_hg[NROW * 4];      // [row][batch]
    __shared__ alignas(16) float sh_xgs[RTH];          // [b][g][il]

    uint32_t rank; asm("mov.u32 %0, %%cluster_ctarank;" : "=r"(rank));
    const int tid = threadIdx.x;
    const int cb = (blockIdx.x >> 3) * BB;

    // ---- load this lane's W slice into registers (64 floats = 32 packed pairs)
    const int w = tid >> 5, lane = tid & 31, rw = lane >> 2, kq = lane & 3;
    const int lr = w * 8 + rw;                 // local row 0..95
    const int g = lr >> 5, il = lr & 31;
    const int grow = g * HDIM + (int)rank * IDXC + il;
    unsigned long long wq[32];
    {
        const ulonglong2* wp = (const ulonglong2*)(W_hh + (size_t)grow * HDIM + kq * 64);
#pragma unroll
        for (int j = 0; j < 16; j++) { ulonglong2 u = wp[j]; wq[2*j] = u.x; wq[2*j+1] = u.y; }
    }
    // ---- per-gate-thread biases (threads 0..127 handle (b, gil))
    float bhr = 0.f, bhz = 0.f, bhn = 0.f;
    if (tid < 128) {
        int gil = tid & 31, gi = (int)rank * IDXC + gil;
        bhr = b_hh[gi]; bhz = b_hh[HDIM + gi]; bhn = b_hh[2 * HDIM + gi];
    }
    // ---- h0 -> buffer 0
    for (int i = tid; i < BB * HDIM; i += RTH) {
        int b = i >> 8, k = i & 255;
        sh_h[0][i] = h0[(size_t)(cb + b) * HDIM + k];
    }
    __syncthreads();
    cluster_barrier();

    // xg loader mapping: tid -> (batch, gate, idx)
    const int lb = tid / 96, rr = tid % 96;
    const size_t xg_base = ((size_t)(cb + lb) * TDIM) * G3
                         + (size_t)(rr >> 5) * HDIM + (size_t)rank * IDXC + (rr & 31);

    const uint32_t h_s = (uint32_t)__cvta_generic_to_shared(sh_h);

    for (int t = 0; t < TDIM; t++) {
        const int cur = t & 1;
        const float* hb = sh_h[cur];

        // prefetch xg for this step (latency hidden under the matvec)
        float xv = g_xg[xg_base + (size_t)t * G3];

        const ulonglong2* hp0 = (const ulonglong2*)(hb + 0 * HDIM + kq * 64);
        const ulonglong2* hp1 = (const ulonglong2*)(hb + 1 * HDIM + kq * 64);
        const ulonglong2* hp2 = (const ulonglong2*)(hb + 2 * HDIM + kq * 64);
        const ulonglong2* hp3 = (const ulonglong2*)(hb + 3 * HDIM + kq * 64);
        unsigned long long a0 = 0ull, a1 = 0ull, a2 = 0ull, a3 = 0ull;
#pragma unroll
        for (int c = 0; c < 16; c++) {
            ulonglong2 v0 = hp0[c]; a0 = fma2(wq[2*c], v0.x, a0); a0 = fma2(wq[2*c+1], v0.y, a0);
            ulonglong2 v1 = hp1[c]; a1 = fma2(wq[2*c], v1.x, a1); a1 = fma2(wq[2*c+1], v1.y, a1);
            ulonglong2 v2 = hp2[c]; a2 = fma2(wq[2*c], v2.x, a2); a2 = fma2(wq[2*c+1], v2.y, a2);
            ulonglong2 v3 = hp3[c]; a3 = fma2(wq[2*c], v3.x, a3); a3 = fma2(wq[2*c+1], v3.y, a3);
        }
        float s0, s1, s2, s3, xl, xh;
        upk2(a0, xl, xh); s0 = xl + xh;
        upk2(a1, xl, xh); s1 = xl + xh;
        upk2(a2, xl, xh); s2 = xl + xh;
        upk2(a3, xl, xh); s3 = xl + xh;
        s0 += __shfl_xor_sync(0xffffffffu, s0, 1); s0 += __shfl_xor_sync(0xffffffffu, s0, 2);
        s1 += __shfl_xor_sync(0xffffffffu, s1, 1); s1 += __shfl_xor_sync(0xffffffffu, s1, 2);
        s2 += __shfl_xor_sync(0xffffffffu, s2, 1); s2 += __shfl_xor_sync(0xffffffffu, s2, 2);
        s3 += __shfl_xor_sync(0xffffffffu, s3, 1); s3 += __shfl_xor_sync(0xffffffffu, s3, 2);
        float outv = (kq == 0) ? s0 : (kq == 1) ? s1 : (kq == 2) ? s2 : s3;
        sh_hg[tid] = outv;           // sh_hg[row*4 + batch] == sh_hg[tid]
        sh_xgs[tid] = xv;
        __syncthreads();

        if (tid < 128) {
            const int b = tid >> 5, gil = tid & 31;
            const int gi = (int)rank * IDXC + gil;
            float xr = sh_xgs[b * 96 + gil];
            float xz = sh_xgs[b * 96 + 32 + gil];
            float xn = sh_xgs[b * 96 + 64 + gil];
            float hr  = sh_hg[gil * 4 + b];
            float hz  = sh_hg[(32 + gil) * 4 + b];
            float hnv = sh_hg[(64 + gil) * 4 + b];
            float hprev = hb[b * HDIM + gi];
            float rg = sigm_f(xr + hr + bhr);
            float zg = sigm_f(xz + hz + bhz);
            float ng = tanh_f(xn + rg * (hnv + bhn));
            float hnew = (1.f - zg) * ng + zg * hprev;

            hs[((size_t)(cb + b) * TDIM + t) * HDIM + gi] = hnew;
            if (t == TDIM - 1) hT[(size_t)(cb + b) * HDIM + gi] = hnew;

            // broadcast hnew pairs into next-h buffer of all 8 CTAs (plain DSMEM stores)
            float hpart = __shfl_down_sync(0xffffffffu, hnew, 1);
            if (t < TDIM - 1 && (gil & 1) == 0) {
                unsigned long long pv = pk2(hnew, hpart);
                uint32_t laddr = h_s + 4u * (uint32_t)((cur ^ 1) * (BB * HDIM) + b * HDIM + gi);
#pragma unroll
                for (uint32_t dr = 0; dr < CLSZ; dr++) st_dsmem_u64(laddr, dr, pv);
            }
        }
        // one cluster barrier per step: publishes DSMEM stores, separates buffers
        cluster_barrier();
    }
}

// ---------------- launch ----------------
extern "C" void kernel_launch(void* const* d_in, const int* in_sizes, int n_in,
                              void* d_out, int out_size) {
    (void)in_sizes; (void)n_in; (void)out_size;
    const float* x    = (const float*)d_in[0];
    const float* h0   = (const float*)d_in[1];
    const float* W_ih = (const float*)d_in[2];
    const float* W_hh = (const float*)d_in[3];
    const float* b_ih = (const float*)d_in[4];
    const float* b_hh = (const float*)d_in[5];
    float* out = (float*)d_out;
    float* hs = out;
    float* hT = out + (size_t)BDIM * TDIM * HDIM;

    dim3 g1((BDIM * TDIM) / BM, G3 / BN);
    proj_gemm<<<g1, 256>>>(x, W_ih, b_ih);

    cudaLaunchConfig_t cfg = {};
    cfg.gridDim = dim3(16 * CLSZ, 1, 1);
    cfg.blockDim = dim3(RTH, 1, 1);
    cfg.dynamicSmemBytes = 0;
    cfg.stream = 0;
    cudaLaunchAttribute attrs[1];
    attrs[0].id = cudaLaunchAttributeClusterDimension;
    attrs[0].val.clusterDim.x = CLSZ;
    attrs[0].val.clusterDim.y = 1;
    attrs[0].val.clusterDim.z = 1;
    cfg.attrs = attrs;
    cfg.numAttrs = 1;
    cudaLaunchKernelEx(&cfg, gru_rec, h0, W_hh, b_hh, hs, hT);
}

// round 5
// speedup vs baseline: 6.2240x; 6.2240x over previous
#include <cuda_runtime.h>
#include <cstdint>

#define BDIM 64
#define TDIM 2048
#define DDIM 256
#define HDIM 256
#define G3   768

// Scratch for the input projection xg = x @ W_ih^T + b_ih : [B*T, 3H] fp32
__device__ float g_xg[(size_t)BDIM * TDIM * G3];

// ---------------- f32x2 helpers ----------------
__device__ __forceinline__ unsigned long long pk2(float x, float y) {
    unsigned long long r;
    asm("mov.b64 %0, {%1, %2};" : "=l"(r) : "f"(x), "f"(y));
    return r;
}
__device__ __forceinline__ void upk2(unsigned long long p, float& x, float& y) {
    asm("mov.b64 {%0, %1}, %2;" : "=f"(x), "=f"(y) : "l"(p));
}
__device__ __forceinline__ unsigned long long fma2(unsigned long long a,
                                                   unsigned long long b,
                                                   unsigned long long c) {
    unsigned long long d;
    asm("fma.rn.f32x2 %0, %1, %2, %3;" : "=l"(d) : "l"(a), "l"(b), "l"(c));
    return d;
}

// ---------------- Kernel 1: projection GEMM (unchanged, known-good) ----------------
#define BM 64
#define BN 64
#define BK 32

__global__ __launch_bounds__(256) void proj_gemm(const float* __restrict__ x,
                                                 const float* __restrict__ W,
                                                 const float* __restrict__ bias) {
    __shared__ float As[BK][BM + 4];
    __shared__ float Bs[BK][BN + 4];
    const int tid = threadIdx.x;
    const int gm = blockIdx.x * BM;
    const int gn = blockIdx.y * BN;
    const int m4 = (tid >> 4) * 4;
    const int n4 = (tid & 15) * 4;

    unsigned long long acc[4][2];
#pragma unroll
    for (int i = 0; i < 4; i++) { acc[i][0] = 0ull; acc[i][1] = 0ull; }

    for (int kt = 0; kt < DDIM; kt += BK) {
#pragma unroll
        for (int j = 0; j < 2; j++) {
            int idx = tid + j * 256;
            int row = idx >> 3;
            int c4  = (idx & 7) * 4;
            float4 va = *(const float4*)&x[(size_t)(gm + row) * DDIM + kt + c4];
            As[c4 + 0][row] = va.x; As[c4 + 1][row] = va.y;
            As[c4 + 2][row] = va.z; As[c4 + 3][row] = va.w;
            float4 vb = *(const float4*)&W[(size_t)(gn + row) * DDIM + kt + c4];
            Bs[c4 + 0][row] = vb.x; Bs[c4 + 1][row] = vb.y;
            Bs[c4 + 2][row] = vb.z; Bs[c4 + 3][row] = vb.w;
        }
        __syncthreads();
#pragma unroll
        for (int k = 0; k < BK; k++) {
            float4 av = *(const float4*)&As[k][m4];
            float4 bv = *(const float4*)&Bs[k][n4];
            unsigned long long bp0 = pk2(bv.x, bv.y);
            unsigned long long bp1 = pk2(bv.z, bv.w);
            unsigned long long aa;
            aa = pk2(av.x, av.x);
            acc[0][0] = fma2(aa, bp0, acc[0][0]); acc[0][1] = fma2(aa, bp1, acc[0][1]);
            aa = pk2(av.y, av.y);
            acc[1][0] = fma2(aa, bp0, acc[1][0]); acc[1][1] = fma2(aa, bp1, acc[1][1]);
            aa = pk2(av.z, av.z);
            acc[2][0] = fma2(aa, bp0, acc[2][0]); acc[2][1] = fma2(aa, bp1, acc[2][1]);
            aa = pk2(av.w, av.w);
            acc[3][0] = fma2(aa, bp0, acc[3][0]); acc[3][1] = fma2(aa, bp1, acc[3][1]);
        }
        __syncthreads();
    }

    float4 bb = *(const float4*)&bias[gn + n4];
#pragma unroll
    for (int mi = 0; mi < 4; mi++) {
        float o0, o1, o2, o3;
        upk2(acc[mi][0], o0, o1);
        upk2(acc[mi][1], o2, o3);
        float4 o = make_float4(o0 + bb.x, o1 + bb.y, o2 + bb.z, o3 + bb.w);
        *(float4*)&g_xg[(size_t)(gm + m4 + mi) * G3 + gn + n4] = o;
    }
}

// ---------------- Kernel 2: CLSZ=4 + register-resident W (index-fixed) ----------------
// 32 clusters x 4 CTAs, cluster owns 2 batches; CTA rank owns 64 h-indices
// (192 W_hh rows). Thread = (k-half, row): W slice of 128 floats in 64 f32x2 regs.
// wq[m] = W pair for k-offset 2m within this thread's 128-wide k-half.
#define CLSZ 4
#define RTH  384
#define IDXC 64
#define NROW 192
#define BB   2

__device__ __forceinline__ float sigm_f(float x) { return 1.f / (1.f + __expf(-x)); }
__device__ __forceinline__ float tanh_f(float x) { return 1.f - 2.f / (__expf(2.f * x) + 1.f); }

__device__ __forceinline__ void st_dsmem_u64(uint32_t saddr, uint32_t rk, unsigned long long v) {
    uint32_t ra;
    asm volatile("mapa.shared::cluster.u32 %0, %1, %2;" : "=r"(ra) : "r"(saddr), "r"(rk));
    asm volatile("st.shared::cluster.u64 [%0], %1;" :: "r"(ra), "l"(v) : "memory");
}
__device__ __forceinline__ void cluster_barrier() {
    asm volatile("barrier.cluster.arrive.aligned;" ::: "memory");
    asm volatile("barrier.cluster.wait.aligned;" ::: "memory");
}

__global__ __launch_bounds__(RTH, 1) void gru_rec(const float* __restrict__ h0,
                                                  const float* __restrict__ W_hh,
                                                  const float* __restrict__ b_hh,
                                                  float* __restrict__ hs,
                                                  float* __restrict__ hT) {
    __shared__ alignas(16) float sh_h[2][BB * HDIM];    // [buf][b][k]
    __shared__ alignas(16) float2 sh_red[NROW];         // kh=1 partials (b0,b1)
    __shared__ alignas(16) float2 sh_hg[NROW];          // full row sums (b0,b1)
    __shared__ alignas(16) float sh_xgs[RTH];           // [b][g][il]

    uint32_t rank; asm("mov.u32 %0, %%cluster_ctarank;" : "=r"(rank));
    const int tid = threadIdx.x;
    const int cb = (blockIdx.x >> 2) * BB;

    // thread mapping: warps 0-5 -> kh=0, warps 6-11 -> kh=1
    const int kh = tid >= NROW;            // k-half
    const int r  = tid - kh * NROW;        // row 0..191
    const int g  = r >> 6, il = r & 63;    // gate, index-in-chunk
    const int grow = g * HDIM + (int)rank * IDXC + il;

    // ---- W slice -> 64 packed f32x2 registers; wq[m] covers k = 2m, 2m+1
    unsigned long long wq[64];
    {
        const ulonglong2* wp = (const ulonglong2*)(W_hh + (size_t)grow * HDIM + kh * 128);
#pragma unroll
        for (int j = 0; j < 32; j++) { ulonglong2 u = wp[j]; wq[2*j] = u.x; wq[2*j+1] = u.y; }
    }
    // ---- gate-thread biases (tid<128: b = tid>>6, gil = tid&63)
    float bhr = 0.f, bhz = 0.f, bhn = 0.f;
    if (tid < 128) {
        int gil = tid & 63, gi = (int)rank * IDXC + gil;
        bhr = b_hh[gi]; bhz = b_hh[HDIM + gi]; bhn = b_hh[2 * HDIM + gi];
    }
    // ---- h0 -> buffer 0
    for (int i = tid; i < BB * HDIM; i += RTH) {
        int b = i >> 8, k = i & 255;
        sh_h[0][i] = h0[(size_t)(cb + b) * HDIM + k];
    }
    __syncthreads();
    cluster_barrier();

    // xg loader mapping: tid -> (batch, gate, idx)
    const int lb = tid / NROW, rr = tid - lb * NROW;
    const size_t xg_base = ((size_t)(cb + lb) * TDIM) * G3
                         + (size_t)(rr >> 6) * HDIM + (size_t)rank * IDXC + (rr & 63);

    const uint32_t h_s = (uint32_t)__cvta_generic_to_shared(sh_h);

    for (int t = 0; t < TDIM; t++) {
        const int cur = t & 1;
        const float* hb = sh_h[cur];

        float xv = g_xg[xg_base + (size_t)t * G3];   // prefetch

        // matvec: hpA[c] covers k-offsets 4c..4c+3 -> pairs wq[2c], wq[2c+1];
        //         hpA[16+c] covers 64+4c..64+4c+3 -> wq[32+2c], wq[32+2c+1]
        const ulonglong2* hpA = (const ulonglong2*)(hb + kh * 128);
        const ulonglong2* hpB = (const ulonglong2*)(hb + HDIM + kh * 128);
        unsigned long long a0 = 0ull, a1 = 0ull;
#pragma unroll
        for (int c = 0; c < 16; c++) {
            ulonglong2 vA = hpA[c];
            a0 = fma2(wq[2*c+0], vA.x, a0); a0 = fma2(wq[2*c+1], vA.y, a0);
            ulonglong2 vB = hpB[c];
            a1 = fma2(wq[2*c+0], vB.x, a1); a1 = fma2(wq[2*c+1], vB.y, a1);
            vA = hpA[16 + c];
            a0 = fma2(wq[32+2*c+0], vA.x, a0); a0 = fma2(wq[32+2*c+1], vA.y, a0);
            vB = hpB[16 + c];
            a1 = fma2(wq[32+2*c+0], vB.x, a1); a1 = fma2(wq[32+2*c+1], vB.y, a1);
        }
        float s0, s1, xl, xh;
        upk2(a0, xl, xh); s0 = xl + xh;
        upk2(a1, xl, xh); s1 = xl + xh;
        if (kh) sh_red[r] = make_float2(s0, s1);
        sh_xgs[tid] = xv;
        __syncthreads();
        if (!kh) {
            float2 p = sh_red[r];
            sh_hg[r] = make_float2(s0 + p.x, s1 + p.y);
        }
        __syncthreads();

        if (tid < 128) {
            const int b = tid >> 6, gil = tid & 63;
            const int gi = (int)rank * IDXC + gil;
            float xr = sh_xgs[b * NROW + gil];
            float xz = sh_xgs[b * NROW + 64 + gil];
            float xn = sh_xgs[b * NROW + 128 + gil];
            float2 hr2 = sh_hg[gil];
            float2 hz2 = sh_hg[64 + gil];
            float2 hn2 = sh_hg[128 + gil];
            float hr  = b ? hr2.y : hr2.x;
            float hz  = b ? hz2.y : hz2.x;
            float hnv = b ? hn2.y : hn2.x;
            float hprev = hb[b * HDIM + gi];
            float rg = sigm_f(xr + hr + bhr);
            float zg = sigm_f(xz + hz + bhz);
            float ng = tanh_f(xn + rg * (hnv + bhn));
            float hnew = (1.f - zg) * ng + zg * hprev;

            hs[((size_t)(cb + b) * TDIM + t) * HDIM + gi] = hnew;
            if (t == TDIM - 1) hT[(size_t)(cb + b) * HDIM + gi] = hnew;

            // broadcast hnew pairs to next-h buffer of all 4 CTAs
            float hpart = __shfl_down_sync(0xffffffffu, hnew, 1);
            if (t < TDIM - 1 && (gil & 1) == 0) {
                unsigned long long pv = pk2(hnew, hpart);
                uint32_t laddr = h_s + 4u * (uint32_t)((cur ^ 1) * (BB * HDIM) + b * HDIM + gi);
#pragma unroll
                for (uint32_t dr = 0; dr < CLSZ; dr++) st_dsmem_u64(laddr, dr, pv);
            }
        }
        cluster_barrier();
    }
}

// ---------------- launch ----------------
extern "C" void kernel_launch(void* const* d_in, const int* in_sizes, int n_in,
                              void* d_out, int out_size) {
    (void)in_sizes; (void)n_in; (void)out_size;
    const float* x    = (const float*)d_in[0];
    const float* h0   = (const float*)d_in[1];
    const float* W_ih = (const float*)d_in[2];
    const float* W_hh = (const float*)d_in[3];
    const float* b_ih = (const float*)d_in[4];
    const float* b_hh = (const float*)d_in[5];
    float* out = (float*)d_out;
    float* hs = out;
    float* hT = out + (size_t)BDIM * TDIM * HDIM;

    dim3 g1((BDIM * TDIM) / BM, G3 / BN);
    proj_gemm<<<g1, 256>>>(x, W_ih, b_ih);

    cudaLaunchConfig_t cfg = {};
    cfg.gridDim = dim3(32 * CLSZ, 1, 1);
    cfg.blockDim = dim3(RTH, 1, 1);
    cfg.dynamicSmemBytes = 0;
    cfg.stream = 0;
    cudaLaunchAttribute attrs[1];
    attrs[0].id = cudaLaunchAttributeClusterDimension;
    attrs[0].val.clusterDim.x = CLSZ;
    attrs[0].val.clusterDim.y = 1;
    attrs[0].val.clusterDim.z = 1;
    cfg.attrs = attrs;
    cfg.numAttrs = 1;
    cudaLaunchKernelEx(&cfg, gru_rec, h0, W_hh, b_hh, hs, hT);
}